// round 9
// baseline (speedup 1.0000x reference)
#include <cuda_runtime.h>
#include <cstdint>
#include <math.h>

#define D_MODEL   256
#define N_HEADS   8
#define LEN_IN    5440
#define LEN_Q     5440
#define BATCH     4
#define M_TOTAL   (BATCH * LEN_Q)   // 21760 = 170 * 128

// k-permutation within groups of 8: pos(k) = [0,4,1,5,2,6,3,7]^-1 mapping
__host__ __device__ __forceinline__ int kperm(int k) {
    return (k & ~7) | ((k & 3) << 1) | ((k >> 2) & 1);
}

// ---------------- scratch (static device globals; no allocation) -------------
__device__ float g_value[(size_t)M_TOTAL * 256];
__device__ float g_off  [(size_t)M_TOTAL * 256];
__device__ float g_attn [(size_t)M_TOTAL * 128];
__device__ float g_mid  [(size_t)M_TOTAL * 256];   // k-permuted + tf32 pre-rounded
// transposed weights [N, K=256] K-major, k-permuted + tf32 pre-rounded
__device__ float g_wvT [256 * 256];
__device__ float g_woT [256 * 256];
__device__ float g_waT [128 * 256];
__device__ float g_wouT[256 * 256];

// ---------------- PTX helpers ------------------------------------------------
__device__ __forceinline__ uint32_t smem_u32(const void* p) {
    uint32_t a;
    asm("{ .reg .u64 t; cvta.to.shared.u64 t, %1; cvt.u32.u64 %0, t; }" : "=r"(a) : "l"(p));
    return a;
}
__device__ __forceinline__ void cp_async16(uint32_t dst, const void* src) {
    asm volatile("cp.async.cg.shared.global [%0], [%1], 16;" :: "r"(dst), "l"(src));
}
#define CP_COMMIT() asm volatile("cp.async.commit_group;" ::: "memory")
#define CP_WAIT(n)  asm volatile("cp.async.wait_group %0;" :: "n"(n) : "memory")

__device__ __forceinline__ uint32_t f2tf(float x) {
    uint32_t r; asm("cvt.rna.tf32.f32 %0, %1;" : "=r"(r) : "f"(x)); return r;
}
__device__ __forceinline__ void mma_tf32(float* c, const uint32_t* a, const uint32_t* b) {
    asm volatile("mma.sync.aligned.m16n8k8.row.col.f32.tf32.tf32.f32 "
        "{%0,%1,%2,%3}, {%4,%5,%6,%7}, {%8,%9}, {%0,%1,%2,%3};"
        : "+f"(c[0]), "+f"(c[1]), "+f"(c[2]), "+f"(c[3])
        : "r"(a[0]), "r"(a[1]), "r"(a[2]), "r"(a[3]), "r"(b[0]), "r"(b[1]));
}

// ------ fused weight transpose + tf32 pre-round + k-permute ------------------
__global__ void transpose_all(const float* __restrict__ Wv, const float* __restrict__ Wo,
                              const float* __restrict__ Wa, const float* __restrict__ Wou,
                              float* __restrict__ WvT, float* __restrict__ WoT,
                              float* __restrict__ WaT, float* __restrict__ WouT) {
    __shared__ float t[32][33];
    const int m = blockIdx.y;
    const float* W; float* Wt; int N;
    if      (m == 0) { W = Wv;  Wt = WvT;  N = 256; }
    else if (m == 1) { W = Wo;  Wt = WoT;  N = 256; }
    else if (m == 2) { W = Wa;  Wt = WaT;  N = 128; }
    else             { W = Wou; Wt = WouT; N = 256; }
    const int bx = (blockIdx.x & 7) * 32;   // n
    const int by = (blockIdx.x >> 3) * 32;  // k
    if (bx >= N) return;
    const int x = threadIdx.x, y = threadIdx.y;
#pragma unroll
    for (int i = 0; i < 32; i += 8) t[y + i][x] = W[(by + y + i) * N + bx + x];
    __syncthreads();
#pragma unroll
    for (int i = 0; i < 32; i += 8)
        Wt[(bx + y + i) * 256 + kperm(by + x)] = __uint_as_float(f2tf(t[x][y + i]));
}

// ---------------- TF32 tensor-core GEMM (3-stage pipeline) -------------------
// CTA tile 128x128, BK=32, 8 warps (2m x 4n), warp tile 64x32 (16x m16n8k8).
// 3-stage cp.async pipeline, constant wait_group<2> via always-commit.
#define TSTRIDE 36
#define TILE_F  (128 * TSTRIDE)
#define BUF_F   (2 * TILE_F)
#define SMEM_B  (3 * BUF_F * 4)     // 110,592 B per CTA

template <bool PRE_A>
__global__ void __launch_bounds__(256, 2)
gemm_tc(const float* __restrict__ A0, const float* __restrict__ A1,
        const float* __restrict__ W0, const float* __restrict__ W1, const float* __restrict__ W2,
        const float* __restrict__ b0, const float* __restrict__ b1, const float* __restrict__ b2,
        float* __restrict__ C0, float* __restrict__ C1, float* __restrict__ C2) {
    extern __shared__ float sm[];
    const int tid  = threadIdx.x;
    const int wid  = tid >> 5;
    const int lane = tid & 31;
    const int gid  = lane >> 2;
    const int tg   = lane & 3;
    const int bm   = blockIdx.x * 128;
    const int mbase = (wid >> 2) * 64;
    const int nbase = (wid & 3) * 32;

    const float *A, *Wt, *bias; float* C; int NTOT = 256; int bn;
    {
        const int y = blockIdx.y;
        if (!PRE_A) {
            if (y < 2)      { A = A0; Wt = W0; bias = b0; C = C0; bn = y * 128; }
            else if (y < 4) { A = A1; Wt = W1; bias = b1; C = C1; bn = (y - 2) * 128; }
            else            { A = A1; Wt = W2; bias = b2; C = C2; bn = 0; NTOT = 128; }
        } else              { A = A0; Wt = W0; bias = b0; C = C0; bn = y * 128; }
    }

    const float* Ab = A  + (size_t)bm * 256;
    const float* Bb = Wt + (size_t)bn * 256;
    const uint32_t smb = smem_u32(sm);

    const int lrow = tid >> 3;
    const int lcol = (tid & 7) * 4;

    // issue loads for one chunk into a stage (no commit)
    auto load_tile = [&](int stage, int kc) {
        const uint32_t dA = smb + (uint32_t)(stage * BUF_F) * 4;
        const uint32_t dB = dA + (uint32_t)TILE_F * 4;
#pragma unroll
        for (int i = 0; i < 4; ++i) {
            const int r = lrow + i * 32;
            const uint32_t off = (uint32_t)(r * TSTRIDE + lcol) * 4;
            cp_async16(dA + off, Ab + (size_t)r * 256 + kc + lcol);
            cp_async16(dB + off, Bb + (size_t)r * 256 + kc + lcol);
        }
    };

    float acc[4][4][4];
#pragma unroll
    for (int mt = 0; mt < 4; ++mt)
#pragma unroll
        for (int nt = 0; nt < 4; ++nt)
#pragma unroll
            for (int i = 0; i < 4; ++i) acc[mt][nt][i] = 0.0f;

    load_tile(0, 0);  CP_COMMIT();
    load_tile(1, 32); CP_COMMIT();

    int stage = 0;
#pragma unroll 1
    for (int c = 0; c < 8; ++c) {
        if (c + 2 < 8) {
            int fill = stage + 2; if (fill >= 3) fill -= 3;
            load_tile(fill, (c + 2) * 32);
        }
        CP_COMMIT();            // possibly empty group -> uniform wait count
        CP_WAIT(2);             // chunk c resident; c+1, c+2 in flight
        __syncthreads();

        const float* As = sm + stage * BUF_F;
        const float* Bs = As + TILE_F;
#pragma unroll
        for (int k8 = 0; k8 < 4; ++k8) {
            const int kk = k8 * 8;
            uint32_t bf[4][2];
#pragma unroll
            for (int nt = 0; nt < 4; ++nt) {
                const int nr = nbase + nt * 8 + gid;
                const float2 b2 = *(const float2*)&Bs[nr * TSTRIDE + kk + 2 * tg];
                bf[nt][0] = __float_as_uint(b2.x);
                bf[nt][1] = __float_as_uint(b2.y);
            }
            uint32_t af[4][4];
#pragma unroll
            for (int mt = 0; mt < 4; ++mt) {
                const int r0 = mbase + mt * 16 + gid;
                if (PRE_A) {
                    const float2 alo = *(const float2*)&As[r0 * TSTRIDE + kk + 2 * tg];
                    const float2 ahi = *(const float2*)&As[(r0 + 8) * TSTRIDE + kk + 2 * tg];
                    af[mt][0] = __float_as_uint(alo.x);
                    af[mt][1] = __float_as_uint(ahi.x);
                    af[mt][2] = __float_as_uint(alo.y);
                    af[mt][3] = __float_as_uint(ahi.y);
                } else {
                    af[mt][0] = f2tf(As[r0 * TSTRIDE + kk + tg]);
                    af[mt][1] = f2tf(As[(r0 + 8) * TSTRIDE + kk + tg]);
                    af[mt][2] = f2tf(As[r0 * TSTRIDE + kk + tg + 4]);
                    af[mt][3] = f2tf(As[(r0 + 8) * TSTRIDE + kk + tg + 4]);
                }
            }
#pragma unroll
            for (int mt = 0; mt < 4; ++mt)
#pragma unroll
                for (int nt = 0; nt < 4; ++nt)
                    mma_tf32(acc[mt][nt], af[mt], bf[nt]);
        }
        __syncthreads();
        stage = (stage == 2) ? 0 : stage + 1;
    }

#pragma unroll
    for (int mt = 0; mt < 4; ++mt) {
        const int row0 = bm + mbase + mt * 16 + gid;
#pragma unroll
        for (int nt = 0; nt < 4; ++nt) {
            const int col = bn + nbase + nt * 8 + tg * 2;
            const float2 bv = *(const float2*)(bias + col);
            float2 v0, v1;
            v0.x = acc[mt][nt][0] + bv.x;  v0.y = acc[mt][nt][1] + bv.y;
            v1.x = acc[mt][nt][2] + bv.x;  v1.y = acc[mt][nt][3] + bv.y;
            *(float2*)(C + (size_t)row0 * NTOT + col)       = v0;
            *(float2*)(C + (size_t)(row0 + 8) * NTOT + col) = v1;
        }
    }
}

// ---------------- sampling ---------------------------------------------------
__global__ void __launch_bounds__(256)
msda_sample(const float* __restrict__ refp) {
    const int bq   = blockIdx.x;
    const int b    = bq / LEN_Q;
    const int tid  = threadIdx.x;
    const int h    = tid >> 5;
    const int lane = tid & 31;

    __shared__ uint4 s_pk[8][16][2];

    const size_t rowo = (size_t)bq * 256;

    {
        const int ln = lane & 15;           // point id
        const int l  = ln >> 2;             // level

        float logit = g_attn[(size_t)bq * 128 + h * 16 + ln];
        float m = logit;
#pragma unroll
        for (int s = 8; s; s >>= 1) m = fmaxf(m, __shfl_xor_sync(0xffffffffu, m, s, 16));
        float e = __expf(logit - m);
        float ssum = e;
#pragma unroll
        for (int s = 8; s; s >>= 1) ssum += __shfl_xor_sync(0xffffffffu, ssum, s, 16);
        const float aw = e / ssum;

        const int S  = 64 >> l;
        const int st = (l == 0) ? 0 : (l == 1) ? 4096 : (l == 2) ? 5120 : 5376;
        const float fs = (float)S;

        const float rx = refp[(size_t)bq * 8 + l * 2 + 0];
        const float ry = refp[(size_t)bq * 8 + l * 2 + 1];
        const float ox = g_off[rowo + h * 32 + ln * 2 + 0];
        const float oy = g_off[rowo + h * 32 + ln * 2 + 1];

        const float x = fmaf(rx, fs, ox) - 0.5f;
        const float y = fmaf(ry, fs, oy) - 0.5f;
        const float x0f = floorf(x), y0f = floorf(y);
        const int ix0 = (int)x0f, iy0 = (int)y0f;
        const float wx = x - x0f, wy = y - y0f;

        const float fx0 = (unsigned)ix0       < (unsigned)S ? 1.0f : 0.0f;
        const float fx1 = (unsigned)(ix0 + 1) < (unsigned)S ? 1.0f : 0.0f;
        const float fy0 = (unsigned)iy0       < (unsigned)S ? 1.0f : 0.0f;
        const float fy1 = (unsigned)(iy0 + 1) < (unsigned)S ? 1.0f : 0.0f;

        const int cx0 = min(max(ix0, 0), S - 1);
        const int cx1 = min(max(ix0 + 1, 0), S - 1);
        const int cy0 = min(max(iy0, 0), S - 1);
        const int cy1 = min(max(iy0 + 1, 0), S - 1);

        if (lane < 16) {
            uint4 left, right;
            left.x  = (uint32_t)((st + cy0 * S + cx0) * 256);
            left.y  = (uint32_t)((st + cy1 * S + cx0) * 256);
            left.z  = __float_as_uint(aw * (1.0f - wx) * (1.0f - wy) * fx0 * fy0);
            left.w  = __float_as_uint(aw * (1.0f - wx) * wy          * fx0 * fy1);
            right.x = (uint32_t)((st + cy0 * S + cx1) * 256);
            right.y = (uint32_t)((st + cy1 * S + cx1) * 256);
            right.z = __float_as_uint(aw * wx * (1.0f - wy) * fx1 * fy0);
            right.w = __float_as_uint(aw * wx * wy          * fx1 * fy1);
            s_pk[h][ln][0] = left;
            s_pk[h][ln][1] = right;
        }
    }
    __syncwarp();

    const int side = lane >> 4;
    const int cb   = (lane & 15) * 2;       // channel pair within head
    const float* vb = g_value + (size_t)b * (LEN_IN * 256) + h * 32 + cb;

    float a0 = 0.f, a1 = 0.f, a2 = 0.f, a3 = 0.f;
#pragma unroll
    for (int p = 0; p < 16; ++p) {
        const uint4 pk = s_pk[h][p][side];
        const float2 vt = *(const float2*)(vb + pk.x);
        const float2 vo = *(const float2*)(vb + pk.y);
        const float wt = __uint_as_float(pk.z);
        const float wb = __uint_as_float(pk.w);
        a0 = fmaf(wt, vt.x, a0);
        a1 = fmaf(wt, vt.y, a1);
        a2 = fmaf(wb, vo.x, a2);
        a3 = fmaf(wb, vo.y, a3);
    }
    float ox_ = a0 + a2;
    float oy_ = a1 + a3;
    ox_ += __shfl_xor_sync(0xffffffffu, ox_, 16);
    oy_ += __shfl_xor_sync(0xffffffffu, oy_, 16);

    if (lane < 16) {   // store pre-rounded tf32 at k-permuted channel positions
        const int c0 = h * 32 + cb;
        g_mid[rowo + kperm(c0)]     = __uint_as_float(f2tf(ox_));
        g_mid[rowo + kperm(c0 + 1)] = __uint_as_float(f2tf(oy_));
    }
}

// ---------------- launch -----------------------------------------------------
extern "C" void kernel_launch(void* const* d_in, const int* in_sizes, int n_in,
                              void* d_out, int out_size) {
    const float* query   = (const float*)d_in[0];
    const float* refp    = (const float*)d_in[1];
    const float* in_flat = (const float*)d_in[2];
    const float* W_val  = (const float*)d_in[5];
    const float* b_val  = (const float*)d_in[6];
    const float* W_off  = (const float*)d_in[7];
    const float* b_off  = (const float*)d_in[8];
    const float* W_attn = (const float*)d_in[9];
    const float* b_attn = (const float*)d_in[10];
    const float* W_out  = (const float*)d_in[11];
    const float* b_out  = (const float*)d_in[12];
    float* out = (float*)d_out;

    float *pv, *po, *pa, *pm, *wvT, *woT, *waT, *wouT;
    cudaGetSymbolAddress((void**)&pv,  g_value);
    cudaGetSymbolAddress((void**)&po,  g_off);
    cudaGetSymbolAddress((void**)&pa,  g_attn);
    cudaGetSymbolAddress((void**)&pm,  g_mid);
    cudaGetSymbolAddress((void**)&wvT, g_wvT);
    cudaGetSymbolAddress((void**)&woT, g_woT);
    cudaGetSymbolAddress((void**)&waT, g_waT);
    cudaGetSymbolAddress((void**)&wouT, g_wouT);

    cudaFuncSetAttribute(gemm_tc<false>, cudaFuncAttributeMaxDynamicSharedMemorySize, SMEM_B);
    cudaFuncSetAttribute(gemm_tc<true>,  cudaFuncAttributeMaxDynamicSharedMemorySize, SMEM_B);

    transpose_all<<<dim3(64, 4), dim3(32, 8)>>>(W_val, W_off, W_attn, W_out,
                                                wvT, woT, waT, wouT);

    // fused front GEMMs: value (y=0,1), offsets (y=2,3), attn (y=4)
    gemm_tc<false><<<dim3(M_TOTAL / 128, 5), 256, SMEM_B>>>(
        in_flat, query, wvT, woT, waT, b_val, b_off, b_attn, pv, po, pa);

    msda_sample<<<M_TOTAL, 256>>>(refp);

    // output projection (A = g_mid, pre-rounded + k-permuted)
    gemm_tc<true><<<dim3(M_TOTAL / 128, 2), 256, SMEM_B>>>(
        pm, nullptr, wouT, nullptr, nullptr, b_out, nullptr, nullptr,
        out, nullptr, nullptr);
}